// round 5
// baseline (speedup 1.0000x reference)
#include <cuda_runtime.h>
#include <cstdint>

// ---------------------------------------------------------------------------
// VectorBasis: out[a,m,o] = sum_{edges e with center a}
//     fc(d_e) * Y_m(e) * sum_n R_n(d_e) * T[sc_a, sn_e, n, o]
// where T[sc,sn,n,o] = sum_q W_alch[sn,q] * emb[sc, n*4+q] * Wc[o, n*4+q]
//
// R5: two launches only.
//   edge_kernel  — R3-proven config (1 edge/thread, staged vecs, scalar
//                  Chebyshev, 3x red.global.add.v4.f32 into (A,12) scratch),
//                  species read directly as int32 (no prep kernel).
//   finalize     — repack + zero-writeback (restores scratch==0 invariant;
//                  g_scratch is zero-initialized at module load).
// ---------------------------------------------------------------------------

#define A_MAX 100000
__device__ float g_scratch[A_MAX * 12];   // invariant: all-zero between calls

__device__ __forceinline__ void red_add_v4(float* p, float a, float b, float c, float d) {
    asm volatile("red.global.add.v4.f32 [%0], {%1, %2, %3, %4};"
                 :: "l"(p), "f"(a), "f"(b), "f"(c), "f"(d)
                 : "memory");
}

__global__ void __launch_bounds__(256)
edge_kernel(const float* __restrict__ vecs,     // (E,3)
            const int*   __restrict__ centers,  // (E,)
            const int*   __restrict__ neighbors,// (E,)
            const int*   __restrict__ species,  // (A,)
            const float* __restrict__ W_alch,   // (4,4)
            const float* __restrict__ emb,      // (4,32)
            const float* __restrict__ Wc,       // (3,32)
            float*       __restrict__ scratch,  // (A,12)
            int E)
{
    // Per-species-pair contraction table, stride 25 (odd -> conflict-free
    // for lane-varying pair index).
    __shared__ float sT[16 * 25];
    __shared__ float sV[256 * 3];
    for (int t = threadIdx.x; t < 16 * 24; t += blockDim.x) {
        int p = t / 24, r = t - p * 24;
        int n = r / 3,  o = r - n * 3;
        int sc = p >> 2, sn = p & 3;
        float v = 0.f;
#pragma unroll
        for (int q = 0; q < 4; q++) {
            int d = n * 4 + q;
            v = fmaf(W_alch[sn * 4 + q] * emb[sc * 32 + d], Wc[o * 32 + d], v);
        }
        sT[p * 25 + r] = v;
    }

    int e0 = blockIdx.x * 256;
    int t  = threadIdx.x;
    int e  = e0 + t;

    float vx, vy, vz;
    if (e0 + 256 <= E) {
        // full block: stage 256 edges' vectors (768 floats = 192 float4)
        const float4* v4 = (const float4*)(vecs + (size_t)e0 * 3);
        if (t < 192) ((float4*)sV)[t] = v4[t];
        __syncthreads();
        vx = sV[t * 3 + 0];
        vy = sV[t * 3 + 1];
        vz = sV[t * 3 + 2];
    } else {
        __syncthreads();
        if (e < E) {
            vx = vecs[(size_t)e * 3 + 0];
            vy = vecs[(size_t)e * 3 + 1];
            vz = vecs[(size_t)e * 3 + 2];
        }
        if (e >= E) return;
    }

    float d2   = fmaf(vx, vx, fmaf(vy, vy, vz * vz)) + 1e-12f;
    float invd = rsqrtf(d2);
    float d    = d2 * invd;

    int a  = centers[e];
    int sc = __ldg(&species[a]);
    int sn = __ldg(&species[neighbors[e]]);
    const float* T = &sT[(sc * 4 + sn) * 25];

    // R_n = sin(n*pi*d/rc)/d via Chebyshev recurrence, invd folded into r1
    float s, c;
    __sincosf(0.62831853071795864769f * d, &s, &c);  // pi/5 * d
    float twoc = 2.0f * c;
    float r_nm1 = 0.0f;
    float r_n   = s * invd;

    float h0 = 0.f, h1 = 0.f, h2 = 0.f;
#pragma unroll
    for (int n = 0; n < 8; n++) {
        h0 = fmaf(r_n, T[n * 3 + 0], h0);
        h1 = fmaf(r_n, T[n * 3 + 1], h1);
        h2 = fmaf(r_n, T[n * 3 + 2], h2);
        float r_np1 = fmaf(twoc, r_n, -r_nm1);
        r_nm1 = r_n;
        r_n   = r_np1;
    }

    // shifted-cosine cutoff (rc=5, width=0.5)
    float fc;
    if (d < 4.5f) {
        fc = 1.0f;
    } else if (d < 5.0f) {
        fc = 0.5f * (__cosf(6.28318530717958647692f * (d - 4.5f)) + 1.0f);
    } else {
        fc = 0.0f;
    }

    float f  = fc * invd;
    float y0 = vy * f;   // m order (-1,0,1) -> (y,z,x)/d
    float y1 = vz * f;
    float y2 = vx * f;

    float* base = scratch + (size_t)a * 12;
    red_add_v4(base + 0, y0 * h0, y0 * h1, y0 * h2, 0.0f);
    red_add_v4(base + 4, y1 * h0, y1 * h1, y1 * h2, 0.0f);
    red_add_v4(base + 8, y2 * h0, y2 * h1, y2 * h2, 0.0f);
}

// 256 atoms/block: coalesced float4 loads of scratch, zero-writeback to
// restore the scratch invariant, shared repack, coalesced float4 stores.
__global__ void __launch_bounds__(256)
finalize_kernel(float4* __restrict__ scratch4, float* __restrict__ out, int A)
{
    __shared__ float sIn[256 * 12];
    __shared__ float sOut[256 * 9];
    int a0 = blockIdx.x * 256;
    int t  = threadIdx.x;
    int valid = A - a0; if (valid > 256) valid = 256;

    int nf4 = valid * 3;
    const float4 z4 = make_float4(0.f, 0.f, 0.f, 0.f);
#pragma unroll
    for (int k = 0; k < 3; k++) {
        int idx = t + 256 * k;
        if (idx < nf4) {
            ((float4*)sIn)[idx] = scratch4[(size_t)a0 * 3 + idx];
            scratch4[(size_t)a0 * 3 + idx] = z4;       // restore zero invariant
        }
    }
    __syncthreads();

    if (t < valid) {
#pragma unroll
        for (int m = 0; m < 3; m++)
#pragma unroll
            for (int o = 0; o < 3; o++)
                sOut[t * 9 + m * 3 + o] = sIn[t * 12 + m * 4 + o];
    }
    __syncthreads();

    if (valid == 256) {
        float4* o4 = (float4*)(out + (size_t)a0 * 9);
#pragma unroll
        for (int k = 0; k < 3; k++) {
            int idx = t + 256 * k;
            if (idx < 576) o4[idx] = ((const float4*)sOut)[idx];
        }
    } else {
        int nf = valid * 9;
        for (int idx = t; idx < nf; idx += 256)
            out[(size_t)a0 * 9 + idx] = sOut[idx];
    }
}

extern "C" void kernel_launch(void* const* d_in, const int* in_sizes, int n_in,
                              void* d_out, int out_size)
{
    const float* vecs      = (const float*)d_in[0];
    const int*   centers   = (const int*)  d_in[1];
    const int*   neighbors = (const int*)  d_in[2];
    const int*   species   = (const int*)  d_in[3];
    // d_in[4], d_in[5] unused by reference
    const float* W_alch    = (const float*)d_in[6];
    const float* emb       = (const float*)d_in[7];
    const float* Wc        = (const float*)d_in[8];

    int E = in_sizes[1];
    int A = in_sizes[3];

    float* scratch = nullptr;
    cudaGetSymbolAddress((void**)&scratch, g_scratch);

    int eblocks = (E + 255) / 256;
    edge_kernel<<<eblocks, 256>>>(vecs, centers, neighbors, species,
                                  W_alch, emb, Wc, scratch, E);

    int ablocks = (A + 255) / 256;
    finalize_kernel<<<ablocks, 256>>>((float4*)scratch, (float*)d_out, A);
}

// round 7
// speedup vs baseline: 1.2452x; 1.2452x over previous
#include <cuda_runtime.h>
#include <cstdint>

// ---------------------------------------------------------------------------
// VectorBasis: out[a,m,o] = sum_{edges e with center a}
//     fc(d_e) * Y_m(e) * sum_n R_n(d_e) * T[sc_a, sn_e, n, o]
// where T[sc,sn,n,o] = sum_q W_alch[sn,q] * emb[sc, n*4+q] * Wc[o, n*4+q]
//
// R7 = R6 with the finalize layout bug fixed:
//   scratch layout is padded m-rows: scratch[a*12 + m*4 + o]  (lane 3 = pad)
//   finalize maps output index j=m*3+o -> slot m*4+o.
// Components (all previously measured):
//   prep     (R3): zero scratch + pack species->u8          ~4.6 us
//   edge_4x  (R4): 4 edges/thread, staged vecs, f32x2 math  ~23.4 us
//   finalize (R2-style, fixed map): thread-per-out-float4   ~5.5 us
// ---------------------------------------------------------------------------

#define A_MAX 100000
__device__ float         g_scratch[A_MAX * 12];
__device__ unsigned char g_spec8[A_MAX + 4];

__device__ __forceinline__ void red_add_v4(float* p, float a, float b, float c, float d) {
    asm volatile("red.global.add.v4.f32 [%0], {%1, %2, %3, %4};"
                 :: "l"(p), "f"(a), "f"(b), "f"(c), "f"(d)
                 : "memory");
}

__device__ __forceinline__ float2 ffma2(float2 a, float2 b, float2 c) {
    float2 r;
    asm("{\n\t"
        ".reg .b64 ra, rb, rc, rd;\n\t"
        "mov.b64 ra, {%2, %3};\n\t"
        "mov.b64 rb, {%4, %5};\n\t"
        "mov.b64 rc, {%6, %7};\n\t"
        "fma.rn.f32x2 rd, ra, rb, rc;\n\t"
        "mov.b64 {%0, %1}, rd;\n\t"
        "}"
        : "=f"(r.x), "=f"(r.y)
        : "f"(a.x), "f"(a.y), "f"(b.x), "f"(b.y), "f"(c.x), "f"(c.y));
    return r;
}
__device__ __forceinline__ float2 fmul2(float2 a, float2 b) {
    float2 r;
    asm("{\n\t"
        ".reg .b64 ra, rb, rd;\n\t"
        "mov.b64 ra, {%2, %3};\n\t"
        "mov.b64 rb, {%4, %5};\n\t"
        "mul.rn.f32x2 rd, ra, rb;\n\t"
        "mov.b64 {%0, %1}, rd;\n\t"
        "}"
        : "=f"(r.x), "=f"(r.y)
        : "f"(a.x), "f"(a.y), "f"(b.x), "f"(b.y));
    return r;
}

// R3-proven prep: zero the scratch (A*12 floats via float4) and pack species->u8.
__global__ void __launch_bounds__(256)
prep_kernel(const int* __restrict__ species, float4* __restrict__ scratch4,
            unsigned char* __restrict__ spec8, int A)
{
    int i = blockIdx.x * blockDim.x + threadIdx.x;
    int n4 = A * 3;
    for (int k = i; k < n4; k += gridDim.x * blockDim.x)
        scratch4[k] = make_float4(0.f, 0.f, 0.f, 0.f);
    for (int k = i; k < A; k += gridDim.x * blockDim.x)
        spec8[k] = (unsigned char)species[k];
}

#define EPB 1024   // edges per block (256 threads x 4)

__device__ __forceinline__ void process_edge(
    float vx, float vy, float vz, int a, int nb,
    const unsigned char* __restrict__ spec8,
    const float2* __restrict__ sTp,
    float* __restrict__ scratch)
{
    float d2   = fmaf(vx, vx, fmaf(vy, vy, vz * vz)) + 1e-12f;
    float invd = rsqrtf(d2);
    float d    = d2 * invd;

    int sc = (int)__ldg(&spec8[a]);
    int sn = (int)__ldg(&spec8[nb]);
    const float2* Tp = &sTp[(sc * 4 + sn) * 13];

    float s, c;
    __sincosf(0.62831853071795864769f * d, &s, &c);  // theta = pi*d/5

    float r1 = s * invd;                 // sin(1*th)/d
    float r2 = (2.0f * c) * r1;          // sin(2*th)/d
    float c2 = fmaf(2.0f * c, c, -1.0f); // cos(2*th)
    float t2 = 2.0f * c2;

    float2 t2v = make_float2(t2, t2);
    float2 rp0 = make_float2(r1, r2);                          // n = 1,2
    float2 rp1 = ffma2(t2v, rp0, make_float2(r1, 0.0f));       // n = 3,4
    float2 rp2 = ffma2(t2v, rp1, make_float2(-rp0.x, -rp0.y)); // n = 5,6
    float2 rp3 = ffma2(t2v, rp2, make_float2(-rp1.x, -rp1.y)); // n = 7,8

    float2 a0 = fmul2(rp0, Tp[0]);
    float2 a1 = fmul2(rp0, Tp[1]);
    float2 a2 = fmul2(rp0, Tp[2]);
    a0 = ffma2(rp1, Tp[3], a0);  a1 = ffma2(rp1, Tp[4],  a1);  a2 = ffma2(rp1, Tp[5],  a2);
    a0 = ffma2(rp2, Tp[6], a0);  a1 = ffma2(rp2, Tp[7],  a1);  a2 = ffma2(rp2, Tp[8],  a2);
    a0 = ffma2(rp3, Tp[9], a0);  a1 = ffma2(rp3, Tp[10], a1);  a2 = ffma2(rp3, Tp[11], a2);
    float h0 = a0.x + a0.y;
    float h1 = a1.x + a1.y;
    float h2 = a2.x + a2.y;

    // shifted-cosine cutoff (rc=5, width=0.5)
    float fc;
    if (d < 4.5f) {
        fc = 1.0f;
    } else if (d < 5.0f) {
        fc = 0.5f * (__cosf(6.28318530717958647692f * (d - 4.5f)) + 1.0f);
    } else {
        fc = 0.0f;
    }

    float f  = fc * invd;
    float y0 = vy * f;   // m order (-1,0,1) -> (y,z,x)/d
    float y1 = vz * f;
    float y2 = vx * f;

    // padded m-row layout: rows m at +0,+4,+8; lane 3 = pad
    float* base = scratch + (size_t)a * 12;
    red_add_v4(base + 0, y0 * h0, y0 * h1, y0 * h2, 0.0f);
    red_add_v4(base + 4, y1 * h0, y1 * h1, y1 * h2, 0.0f);
    red_add_v4(base + 8, y2 * h0, y2 * h1, y2 * h2, 0.0f);
}

__global__ void __launch_bounds__(256)
edge_kernel(const float*         __restrict__ vecs,     // (E,3)
            const int*           __restrict__ centers,  // (E,)
            const int*           __restrict__ neighbors,// (E,)
            const unsigned char* __restrict__ spec8,    // (A,)
            const float*         __restrict__ W_alch,   // (4,4)
            const float*         __restrict__ emb,      // (4,32)
            const float*         __restrict__ Wc,       // (3,32)
            float*               __restrict__ scratch,  // (A,12)
            int E)
{
    // T table as n-pairs: sTp[pair*13 + k*3 + o] = (T[2k,o], T[2k+1,o])
    __shared__ float2 sTp[16 * 13];
    __shared__ float  sV[EPB * 3];   // 12 KB staged vectors

    {
        int t = threadIdx.x;
        if (t < 192) {
            int p = t / 12, r = t - p * 12;
            int k = r / 3,  o = r - k * 3;
            int sc = p >> 2, sn = p & 3;
            float lo = 0.f, hi = 0.f;
#pragma unroll
            for (int q = 0; q < 4; q++) {
                int d0 = (2 * k) * 4 + q;
                int d1 = (2 * k + 1) * 4 + q;
                float w = W_alch[sn * 4 + q];
                lo = fmaf(w * emb[sc * 32 + d0], Wc[o * 32 + d0], lo);
                hi = fmaf(w * emb[sc * 32 + d1], Wc[o * 32 + d1], hi);
            }
            sTp[p * 13 + r] = make_float2(lo, hi);
        }
    }

    int e0   = blockIdx.x * EPB;
    bool full = (e0 + EPB <= E);
    int t = threadIdx.x;

    if (full) {
        const float4* v4 = (const float4*)(vecs + (size_t)e0 * 3);
#pragma unroll
        for (int k = 0; k < 3; k++)
            ((float4*)sV)[t + 256 * k] = v4[t + 256 * k];
    }
    __syncthreads();

    int base = e0 + t * 4;
    if (full) {
        int4 cc = *(const int4*)(centers   + base);
        int4 nn = *(const int4*)(neighbors + base);
        float4 va = ((const float4*)sV)[t * 3 + 0];
        float4 vb = ((const float4*)sV)[t * 3 + 1];
        float4 vc = ((const float4*)sV)[t * 3 + 2];
        process_edge(va.x, va.y, va.z, cc.x, nn.x, spec8, sTp, scratch);
        process_edge(va.w, vb.x, vb.y, cc.y, nn.y, spec8, sTp, scratch);
        process_edge(vb.z, vb.w, vc.x, cc.z, nn.z, spec8, sTp, scratch);
        process_edge(vc.y, vc.z, vc.w, cc.w, nn.w, spec8, sTp, scratch);
    } else {
#pragma unroll
        for (int j = 0; j < 4; j++) {
            int e = base + j;
            if (e < E) {
                float vx = vecs[(size_t)e * 3 + 0];
                float vy = vecs[(size_t)e * 3 + 1];
                float vz = vecs[(size_t)e * 3 + 2];
                process_edge(vx, vy, vz, centers[e], neighbors[e], spec8, sTp, scratch);
            }
        }
    }
}

// Finalize: one thread per float4 of output; gather from PADDED layout:
// output index j = m*3+o  ->  scratch slot m*4+o.
__global__ void __launch_bounds__(256)
finalize_kernel(const float* __restrict__ scratch, float4* __restrict__ out, int total4)
{
    int i = blockIdx.x * blockDim.x + threadIdx.x;
    if (i >= total4) return;
    int f = i * 4;
    float v[4];
#pragma unroll
    for (int k = 0; k < 4; k++) {
        unsigned ff = f + k;
        unsigned a  = ff / 9u;
        unsigned j  = ff - a * 9u;
        unsigned m  = j / 3u;
        unsigned o  = j - m * 3u;
        v[k] = scratch[a * 12u + m * 4u + o];
    }
    out[i] = make_float4(v[0], v[1], v[2], v[3]);
}

__global__ void __launch_bounds__(256)
finalize_tail(const float* __restrict__ scratch, float* __restrict__ out, int start, int total)
{
    int i = start + blockIdx.x * blockDim.x + threadIdx.x;
    if (i >= total) return;
    unsigned a = (unsigned)i / 9u;
    unsigned j = (unsigned)i - a * 9u;
    unsigned m = j / 3u;
    unsigned o = j - m * 3u;
    out[i] = scratch[a * 12u + m * 4u + o];
}

extern "C" void kernel_launch(void* const* d_in, const int* in_sizes, int n_in,
                              void* d_out, int out_size)
{
    const float* vecs      = (const float*)d_in[0];
    const int*   centers   = (const int*)  d_in[1];
    const int*   neighbors = (const int*)  d_in[2];
    const int*   species   = (const int*)  d_in[3];
    // d_in[4], d_in[5] unused by reference
    const float* W_alch    = (const float*)d_in[6];
    const float* emb       = (const float*)d_in[7];
    const float* Wc        = (const float*)d_in[8];

    int E = in_sizes[1];
    int A = in_sizes[3];

    float* scratch = nullptr;
    cudaGetSymbolAddress((void**)&scratch, g_scratch);
    unsigned char* spec8 = nullptr;
    cudaGetSymbolAddress((void**)&spec8, g_spec8);

    prep_kernel<<<592, 256>>>(species, (float4*)scratch, spec8, A);

    int eblocks = (E + EPB - 1) / EPB;
    edge_kernel<<<eblocks, 256>>>(vecs, centers, neighbors, spec8,
                                  W_alch, emb, Wc, scratch, E);

    int total  = A * 9;
    int total4 = total / 4;
    if (total4 > 0)
        finalize_kernel<<<(total4 + 255) / 256, 256>>>(scratch, (float4*)d_out, total4);
    int done = total4 * 4;
    if (done < total)
        finalize_tail<<<1, 256>>>(scratch, (float*)d_out, done, total);
}

// round 8
// speedup vs baseline: 1.2543x; 1.0073x over previous
#include <cuda_runtime.h>
#include <cstdint>

// ---------------------------------------------------------------------------
// VectorBasis: out[a,m,o] = sum_{edges e with center a}
//     fc(d_e) * Y_m(e) * sum_n R_n(d_e) * T[sc_a, sn_e, n, o]
// where T[sc,sn,n,o] = sum_q W_alch[sn,q] * emb[sc, n*4+q] * Wc[o, n*4+q]
//
// R8:
//   prep     — single-pass (1 float4 zero-store/thread + uchar4 pack)
//   edge     — 4 edges/thread staged loads (R4/R7) + SCALAR math (R3):
//              isolates "f32x2 packed math vs scalar" at fixed load structure
//   finalize — R7-proven thread-per-out-float4 gather from padded layout
// Scratch layout: padded m-rows scratch[a*12 + m*4 + o], lane 3 = pad.
// ---------------------------------------------------------------------------

#define A_MAX 100000
__device__ float         g_scratch[A_MAX * 12];
__device__ unsigned char g_spec8[A_MAX + 4];

__device__ __forceinline__ void red_add_v4(float* p, float a, float b, float c, float d) {
    asm volatile("red.global.add.v4.f32 [%0], {%1, %2, %3, %4};"
                 :: "l"(p), "f"(a), "f"(b), "f"(c), "f"(d)
                 : "memory");
}

// Single-pass prep: thread i zeroes scratch4[i] (i < A*3); threads [0, A/4)
// also pack species int4 -> uchar4.
__global__ void __launch_bounds__(256)
prep_kernel(const int4* __restrict__ species4, const int* __restrict__ species,
            float4* __restrict__ scratch4, uchar4* __restrict__ spec8_4,
            unsigned char* __restrict__ spec8, int A)
{
    int i = blockIdx.x * blockDim.x + threadIdx.x;
    int n4 = A * 3;
    if (i < n4)
        scratch4[i] = make_float4(0.f, 0.f, 0.f, 0.f);
    int np = A >> 2;
    if (i < np) {
        int4 s = species4[i];
        spec8_4[i] = make_uchar4((unsigned char)s.x, (unsigned char)s.y,
                                 (unsigned char)s.z, (unsigned char)s.w);
    }
    if (i == np) {
        for (int j = np * 4; j < A; j++) spec8[j] = (unsigned char)species[j];
    }
}

#define EPB 1024   // edges per block (256 threads x 4)

__device__ __forceinline__ void process_edge(
    float vx, float vy, float vz, int a, int nb,
    const unsigned char* __restrict__ spec8,
    const float* __restrict__ sT,
    float* __restrict__ scratch)
{
    float d2   = fmaf(vx, vx, fmaf(vy, vy, vz * vz)) + 1e-12f;
    float invd = rsqrtf(d2);
    float d    = d2 * invd;

    int sc = (int)__ldg(&spec8[a]);
    int sn = (int)__ldg(&spec8[nb]);
    const float* T = &sT[(sc * 4 + sn) * 25];

    // R_n = sin(n*pi*d/rc)/d via scalar Chebyshev recurrence
    float s, c;
    __sincosf(0.62831853071795864769f * d, &s, &c);  // pi/5 * d
    float twoc = 2.0f * c;
    float r_nm1 = 0.0f;
    float r_n   = s * invd;

    float h0 = 0.f, h1 = 0.f, h2 = 0.f;
#pragma unroll
    for (int n = 0; n < 8; n++) {
        h0 = fmaf(r_n, T[n * 3 + 0], h0);
        h1 = fmaf(r_n, T[n * 3 + 1], h1);
        h2 = fmaf(r_n, T[n * 3 + 2], h2);
        float r_np1 = fmaf(twoc, r_n, -r_nm1);
        r_nm1 = r_n;
        r_n   = r_np1;
    }

    // shifted-cosine cutoff (rc=5, width=0.5)
    float fc;
    if (d < 4.5f) {
        fc = 1.0f;
    } else if (d < 5.0f) {
        fc = 0.5f * (__cosf(6.28318530717958647692f * (d - 4.5f)) + 1.0f);
    } else {
        fc = 0.0f;
    }

    float f  = fc * invd;
    float y0 = vy * f;   // m order (-1,0,1) -> (y,z,x)/d
    float y1 = vz * f;
    float y2 = vx * f;

    // padded m-row layout: rows m at +0,+4,+8; lane 3 = pad
    float* base = scratch + (size_t)a * 12;
    red_add_v4(base + 0, y0 * h0, y0 * h1, y0 * h2, 0.0f);
    red_add_v4(base + 4, y1 * h0, y1 * h1, y1 * h2, 0.0f);
    red_add_v4(base + 8, y2 * h0, y2 * h1, y2 * h2, 0.0f);
}

__global__ void __launch_bounds__(256)
edge_kernel(const float*         __restrict__ vecs,     // (E,3)
            const int*           __restrict__ centers,  // (E,)
            const int*           __restrict__ neighbors,// (E,)
            const unsigned char* __restrict__ spec8,    // (A,)
            const float*         __restrict__ W_alch,   // (4,4)
            const float*         __restrict__ emb,      // (4,32)
            const float*         __restrict__ Wc,       // (3,32)
            float*               __restrict__ scratch,  // (A,12)
            int E)
{
    // Per-species-pair contraction table, stride 25 (odd -> conflict-free
    // for lane-varying pair index).
    __shared__ float sT[16 * 25];
    __shared__ float sV[EPB * 3];   // 12 KB staged vectors

    for (int t = threadIdx.x; t < 16 * 24; t += blockDim.x) {
        int p = t / 24, r = t - p * 24;
        int n = r / 3,  o = r - n * 3;
        int sc = p >> 2, sn = p & 3;
        float v = 0.f;
#pragma unroll
        for (int q = 0; q < 4; q++) {
            int d = n * 4 + q;
            v = fmaf(W_alch[sn * 4 + q] * emb[sc * 32 + d], Wc[o * 32 + d], v);
        }
        sT[p * 25 + r] = v;
    }

    int e0   = blockIdx.x * EPB;
    bool full = (e0 + EPB <= E);
    int t = threadIdx.x;

    if (full) {
        const float4* v4 = (const float4*)(vecs + (size_t)e0 * 3);
#pragma unroll
        for (int k = 0; k < 3; k++)
            ((float4*)sV)[t + 256 * k] = v4[t + 256 * k];
    }
    __syncthreads();

    int base = e0 + t * 4;
    if (full) {
        int4 cc = *(const int4*)(centers   + base);
        int4 nn = *(const int4*)(neighbors + base);
        float4 va = ((const float4*)sV)[t * 3 + 0];
        float4 vb = ((const float4*)sV)[t * 3 + 1];
        float4 vc = ((const float4*)sV)[t * 3 + 2];
        process_edge(va.x, va.y, va.z, cc.x, nn.x, spec8, sT, scratch);
        process_edge(va.w, vb.x, vb.y, cc.y, nn.y, spec8, sT, scratch);
        process_edge(vb.z, vb.w, vc.x, cc.z, nn.z, spec8, sT, scratch);
        process_edge(vc.y, vc.z, vc.w, cc.w, nn.w, spec8, sT, scratch);
    } else {
#pragma unroll
        for (int j = 0; j < 4; j++) {
            int e = base + j;
            if (e < E) {
                float vx = vecs[(size_t)e * 3 + 0];
                float vy = vecs[(size_t)e * 3 + 1];
                float vz = vecs[(size_t)e * 3 + 2];
                process_edge(vx, vy, vz, centers[e], neighbors[e], spec8, sT, scratch);
            }
        }
    }
}

// Finalize: one thread per float4 of output; gather from PADDED layout:
// output index j = m*3+o  ->  scratch slot m*4+o.
__global__ void __launch_bounds__(256)
finalize_kernel(const float* __restrict__ scratch, float4* __restrict__ out, int total4)
{
    int i = blockIdx.x * blockDim.x + threadIdx.x;
    if (i >= total4) return;
    int f = i * 4;
    float v[4];
#pragma unroll
    for (int k = 0; k < 4; k++) {
        unsigned ff = f + k;
        unsigned a  = ff / 9u;
        unsigned j  = ff - a * 9u;
        unsigned m  = j / 3u;
        unsigned o  = j - m * 3u;
        v[k] = scratch[a * 12u + m * 4u + o];
    }
    out[i] = make_float4(v[0], v[1], v[2], v[3]);
}

__global__ void __launch_bounds__(256)
finalize_tail(const float* __restrict__ scratch, float* __restrict__ out, int start, int total)
{
    int i = start + blockIdx.x * blockDim.x + threadIdx.x;
    if (i >= total) return;
    unsigned a = (unsigned)i / 9u;
    unsigned j = (unsigned)i - a * 9u;
    unsigned m = j / 3u;
    unsigned o = j - m * 3u;
    out[i] = scratch[a * 12u + m * 4u + o];
}

extern "C" void kernel_launch(void* const* d_in, const int* in_sizes, int n_in,
                              void* d_out, int out_size)
{
    const float* vecs      = (const float*)d_in[0];
    const int*   centers   = (const int*)  d_in[1];
    const int*   neighbors = (const int*)  d_in[2];
    const int*   species   = (const int*)  d_in[3];
    // d_in[4], d_in[5] unused by reference
    const float* W_alch    = (const float*)d_in[6];
    const float* emb       = (const float*)d_in[7];
    const float* Wc        = (const float*)d_in[8];

    int E = in_sizes[1];
    int A = in_sizes[3];

    float* scratch = nullptr;
    cudaGetSymbolAddress((void**)&scratch, g_scratch);
    unsigned char* spec8 = nullptr;
    cudaGetSymbolAddress((void**)&spec8, g_spec8);

    int pn = A * 3 + 1;                       // covers zeroing range and pack range
    prep_kernel<<<(pn + 255) / 256, 256>>>((const int4*)species, species,
                                           (float4*)scratch, (uchar4*)spec8,
                                           spec8, A);

    int eblocks = (E + EPB - 1) / EPB;
    edge_kernel<<<eblocks, 256>>>(vecs, centers, neighbors, spec8,
                                  W_alch, emb, Wc, scratch, E);

    int total  = A * 9;
    int total4 = total / 4;
    if (total4 > 0)
        finalize_kernel<<<(total4 + 255) / 256, 256>>>(scratch, (float4*)d_out, total4);
    int done = total4 * 4;
    if (done < total)
        finalize_tail<<<1, 256>>>(scratch, (float*)d_out, done, total);
}